// round 4
// baseline (speedup 1.0000x reference)
#include <cuda_runtime.h>
#include <cstdint>
#include <math.h>

// ---------------- problem constants (fixed shapes) ----------------
#define NN 100000      // nodes
#define EE 400000      // edges (without self loops)
#define ET (EE + NN)   // total edges incl self loops
#define F0 128         // input features
#define HID 256        // hidden (4 heads x 64)
#define OUTC 128       // output features
#define SLOPE 0.2f

// ---------------- device scratch (no allocations allowed) ----------------
// Referenced ONLY from device code — no cudaGetSymbolAddress anywhere.
__device__ __align__(16) float g_h[(size_t)NN * HID];     // GEMM output of current layer
__device__ __align__(16) float g_agg[(size_t)NN * HID];   // aggregated output (next layer input)
__device__ __align__(16) float g_als[(size_t)NN * 4];
__device__ __align__(16) float g_ald[(size_t)NN * 4];
__device__ int   g_deg[NN];
__device__ int   g_off[NN + 1];
__device__ int   g_cur[NN];
__device__ int   g_csr[ET];
__device__ int   g_is64;   // 1 if edge_index is int64, 0 if int32

// ---------------- edge-index dtype probe ----------------
// int64 node ids < 2^31 have all-zero odd 32-bit words; int32 data has random
// node ids there. 128 samples -> false positive probability ~0.
__global__ void k_detect(const int* __restrict__ ei32) {
    if (threadIdx.x == 0 && blockIdx.x == 0) {
        int odd_nonzero = 0;
        for (int i = 1; i < 256; i += 2) odd_nonzero += (ei32[i] != 0);
        g_is64 = (odd_nonzero == 0) ? 1 : 0;
    }
}

__device__ __forceinline__ int edge_at(const void* __restrict__ ei, size_t idx) {
    if (g_is64) return (int)((const long long*)ei)[idx];
    return ((const int*)ei)[idx];
}

// ---------------- CSR build ----------------
__global__ void k_init_deg() {
    int i = blockIdx.x * blockDim.x + threadIdx.x;
    if (i < NN) g_deg[i] = 1;   // self loop
}

__global__ void k_count_edges(const void* __restrict__ ei) {
    int i = blockIdx.x * blockDim.x + threadIdx.x;
    if (i < EE) atomicAdd(&g_deg[edge_at(ei, (size_t)EE + i)], 1);
}

__global__ void k_scan() {  // <<<1,1024>>>
    __shared__ int sh[1024];
    const int t = threadIdx.x;
    const int CH = (NN + 1023) / 1024;
    int s0 = t * CH;
    int s1 = s0 + CH; if (s1 > NN) s1 = NN; if (s0 > NN) s0 = NN;
    int sum = 0;
    for (int i = s0; i < s1; i++) sum += g_deg[i];
    sh[t] = sum;
    __syncthreads();
    for (int o = 1; o < 1024; o <<= 1) {
        int v = (t >= o) ? sh[t - o] : 0;
        __syncthreads();
        sh[t] += v;
        __syncthreads();
    }
    int run = (t == 0) ? 0 : sh[t - 1];
    for (int i = s0; i < s1; i++) { g_off[i] = run; run += g_deg[i]; }
    if (t == 1023) g_off[NN] = run;
}

__global__ void k_scatter_self() {
    int i = blockIdx.x * blockDim.x + threadIdx.x;
    if (i < NN) { int o = g_off[i]; g_csr[o] = i; g_cur[i] = o + 1; }
}

__global__ void k_scatter_edges(const void* __restrict__ ei) {
    int i = blockIdx.x * blockDim.x + threadIdx.x;
    if (i < EE) {
        int d = edge_at(ei, (size_t)EE + i);
        int p = atomicAdd(&g_cur[d], 1);
        g_csr[p] = edge_at(ei, i);
    }
}

// ---------------- fp32 tiled GEMM: g_h[M,Nc] = A[M,K] @ B[K,Nc] ----------------
// A = external input (x) if USE_EXT_A, else g_agg. C is always g_h.
// BM=128, BN=128, BK=16, 256 threads, 8x8 per thread. K % 16 == 0, Nc % 128 == 0.
template <bool USE_EXT_A>
__global__ __launch_bounds__(256) void k_sgemm(const float* __restrict__ Aext,
                                               const float* __restrict__ B,
                                               int M, int K, int Nc) {
    const float* __restrict__ A = USE_EXT_A ? Aext : (const float*)g_agg;
    float* __restrict__ C = g_h;

    __shared__ float As[16][128];
    __shared__ float Bs[16][128];
    const int tid = threadIdx.x;
    const int tx = tid & 15;
    const int ty = tid >> 4;
    const int rowBase = blockIdx.x * 128;
    const int colBase = blockIdx.y * 128;

    float acc[8][8];
#pragma unroll
    for (int i = 0; i < 8; i++)
#pragma unroll
        for (int j = 0; j < 8; j++) acc[i][j] = 0.f;

    for (int k0 = 0; k0 < K; k0 += 16) {
        // load A tile (128 x 16), transpose into As[k][m]
#pragma unroll
        for (int it = 0; it < 2; it++) {
            int idx = tid + it * 256;       // 0..511
            int ar = idx >> 2;              // 0..127
            int ac = (idx & 3) * 4;         // 0,4,8,12
            float4 v = make_float4(0.f, 0.f, 0.f, 0.f);
            int gr = rowBase + ar;
            if (gr < M) v = *(const float4*)(A + (size_t)gr * K + k0 + ac);
            As[ac + 0][ar] = v.x; As[ac + 1][ar] = v.y;
            As[ac + 2][ar] = v.z; As[ac + 3][ar] = v.w;
        }
        // load B tile (16 x 128)
#pragma unroll
        for (int it = 0; it < 2; it++) {
            int idx = tid + it * 256;
            int br = idx >> 5;              // 0..15
            int bc = (idx & 31) * 4;        // 0..124
            float4 v = *(const float4*)(B + (size_t)(k0 + br) * Nc + colBase + bc);
            *(float4*)(&Bs[br][bc]) = v;
        }
        __syncthreads();
#pragma unroll
        for (int k = 0; k < 16; k++) {
            float ra[8], rb[8];
#pragma unroll
            for (int i = 0; i < 8; i++) ra[i] = As[k][ty * 8 + i];
#pragma unroll
            for (int j = 0; j < 8; j++) rb[j] = Bs[k][tx * 8 + j];
#pragma unroll
            for (int i = 0; i < 8; i++)
#pragma unroll
                for (int j = 0; j < 8; j++) acc[i][j] = fmaf(ra[i], rb[j], acc[i][j]);
        }
        __syncthreads();
    }
#pragma unroll
    for (int i = 0; i < 8; i++) {
        int gr = rowBase + ty * 8 + i;
        if (gr < M) {
            float* cp = C + (size_t)gr * Nc + colBase + tx * 8;
            *(float4*)(cp + 0) = make_float4(acc[i][0], acc[i][1], acc[i][2], acc[i][3]);
            *(float4*)(cp + 4) = make_float4(acc[i][4], acc[i][5], acc[i][6], acc[i][7]);
        }
    }
}

// ---------------- per-node attention scores ----------------
// g_als[n][h] = dot(g_h[n, h*C : h*C+C], a_src[h]); same for g_ald.
template <int CT, int H>
__global__ __launch_bounds__(256) void k_scores(const float* __restrict__ a_s,
                                                const float* __restrict__ a_d) {
    int wid = (blockIdx.x * blockDim.x + threadIdx.x) >> 5;
    int lane = threadIdx.x & 31;
    if (wid >= NN) return;
    const float* hp = g_h + (size_t)wid * CT;

    int cA = lane * 4;
    float4 hv = *(const float4*)(hp + cA);
    float4 sv = *(const float4*)(a_s + cA);
    float4 dv = *(const float4*)(a_d + cA);
    float psA = hv.x * sv.x + hv.y * sv.y + hv.z * sv.z + hv.w * sv.w;
    float pdA = hv.x * dv.x + hv.y * dv.y + hv.z * dv.z + hv.w * dv.w;

    if (CT == 256) {
        int cB = 128 + lane * 4;
        float4 hv2 = *(const float4*)(hp + cB);
        float4 sv2 = *(const float4*)(a_s + cB);
        float4 dv2 = *(const float4*)(a_d + cB);
        float psB = hv2.x * sv2.x + hv2.y * sv2.y + hv2.z * sv2.z + hv2.w * sv2.w;
        float pdB = hv2.x * dv2.x + hv2.y * dv2.y + hv2.z * dv2.z + hv2.w * dv2.w;
        // reduce within 16-lane groups (heads split at lane 16)
#pragma unroll
        for (int o = 8; o; o >>= 1) {
            psA += __shfl_xor_sync(0xffffffffu, psA, o);
            pdA += __shfl_xor_sync(0xffffffffu, pdA, o);
            psB += __shfl_xor_sync(0xffffffffu, psB, o);
            pdB += __shfl_xor_sync(0xffffffffu, pdB, o);
        }
        if (lane == 0)  { g_als[wid * 4 + 0] = psA; g_ald[wid * 4 + 0] = pdA;
                          g_als[wid * 4 + 2] = psB; g_ald[wid * 4 + 2] = pdB; }
        if (lane == 16) { g_als[wid * 4 + 1] = psA; g_ald[wid * 4 + 1] = pdA;
                          g_als[wid * 4 + 3] = psB; g_ald[wid * 4 + 3] = pdB; }
    } else {
#pragma unroll
        for (int o = 16; o; o >>= 1) {
            psA += __shfl_xor_sync(0xffffffffu, psA, o);
            pdA += __shfl_xor_sync(0xffffffffu, pdA, o);
        }
        if (lane == 0) { g_als[wid] = psA; g_ald[wid] = pdA; }
    }
}

__device__ __forceinline__ float lrelu(float x) { return x > 0.f ? x : SLOPE * x; }
__device__ __forceinline__ float elu(float x)   { return x > 0.f ? x : expm1f(x); }

// ---------------- warp-per-dst-node softmax + aggregation ----------------
// Reads g_h / g_als / g_ald / g_off / g_csr; writes g_agg, or extOut if EXT_OUT.
template <int CT, int H, bool DO_ELU, bool EXT_OUT>
__global__ __launch_bounds__(256) void k_agg(const float* __restrict__ bias,
                                             float* __restrict__ extOut) {
    int n = (blockIdx.x * blockDim.x + threadIdx.x) >> 5;
    int lane = threadIdx.x & 31;
    if (n >= NN) return;
    float* __restrict__ out = EXT_OUT ? extOut : (float*)g_agg;
    const int beg = g_off[n], end = g_off[n + 1];
    const float* __restrict__ h = g_h;
    const float* __restrict__ als = g_als;
    const float* __restrict__ ald = g_ald;

    if (H == 4) {
        float4 ad = *(const float4*)(ald + (size_t)n * 4);
        // pass 1: max per head
        float4 m = make_float4(-INFINITY, -INFINITY, -INFINITY, -INFINITY);
        for (int i = beg + lane; i < end; i += 32) {
            int s = g_csr[i];
            float4 as = *(const float4*)(als + (size_t)s * 4);
            m.x = fmaxf(m.x, lrelu(as.x + ad.x));
            m.y = fmaxf(m.y, lrelu(as.y + ad.y));
            m.z = fmaxf(m.z, lrelu(as.z + ad.z));
            m.w = fmaxf(m.w, lrelu(as.w + ad.w));
        }
#pragma unroll
        for (int o = 16; o; o >>= 1) {
            m.x = fmaxf(m.x, __shfl_xor_sync(0xffffffffu, m.x, o));
            m.y = fmaxf(m.y, __shfl_xor_sync(0xffffffffu, m.y, o));
            m.z = fmaxf(m.z, __shfl_xor_sync(0xffffffffu, m.z, o));
            m.w = fmaxf(m.w, __shfl_xor_sync(0xffffffffu, m.w, o));
        }
        // pass 2: sum of exp
        float4 den = make_float4(0.f, 0.f, 0.f, 0.f);
        for (int i = beg + lane; i < end; i += 32) {
            int s = g_csr[i];
            float4 as = *(const float4*)(als + (size_t)s * 4);
            den.x += __expf(lrelu(as.x + ad.x) - m.x);
            den.y += __expf(lrelu(as.y + ad.y) - m.y);
            den.z += __expf(lrelu(as.z + ad.z) - m.z);
            den.w += __expf(lrelu(as.w + ad.w) - m.w);
        }
#pragma unroll
        for (int o = 16; o; o >>= 1) {
            den.x += __shfl_xor_sync(0xffffffffu, den.x, o);
            den.y += __shfl_xor_sync(0xffffffffu, den.y, o);
            den.z += __shfl_xor_sync(0xffffffffu, den.z, o);
            den.w += __shfl_xor_sync(0xffffffffu, den.w, o);
        }
        float4 inv = make_float4(1.f / (den.x + 1e-16f), 1.f / (den.y + 1e-16f),
                                 1.f / (den.z + 1e-16f), 1.f / (den.w + 1e-16f));
        // pass 3: aggregate; lane owns channels [lane*4, +4) and [128+lane*4, +4)
        const int hA = lane >> 4;                 // head owning first-half channels
        const float adA = hA ? ad.y : ad.x;
        const float adB = hA ? ad.w : ad.z;
        const float mA  = hA ? m.y  : m.x;
        const float mB  = hA ? m.w  : m.z;
        const float ivA = hA ? inv.y : inv.x;
        const float ivB = hA ? inv.w : inv.z;
        const int cA = lane * 4;
        const int cB = 128 + lane * 4;
        float acc[8] = {0.f, 0.f, 0.f, 0.f, 0.f, 0.f, 0.f, 0.f};
        for (int i = beg; i < end; i++) {
            int s = g_csr[i];
            float4 as = *(const float4*)(als + (size_t)s * 4);
            float asA = hA ? as.y : as.x;
            float asB = hA ? as.w : as.z;
            float alA = __expf(lrelu(asA + adA) - mA) * ivA;
            float alB = __expf(lrelu(asB + adB) - mB) * ivB;
            const float* hp = h + (size_t)s * 256;
            float4 v0 = *(const float4*)(hp + cA);
            float4 v1 = *(const float4*)(hp + cB);
            acc[0] = fmaf(alA, v0.x, acc[0]); acc[1] = fmaf(alA, v0.y, acc[1]);
            acc[2] = fmaf(alA, v0.z, acc[2]); acc[3] = fmaf(alA, v0.w, acc[3]);
            acc[4] = fmaf(alB, v1.x, acc[4]); acc[5] = fmaf(alB, v1.y, acc[5]);
            acc[6] = fmaf(alB, v1.z, acc[6]); acc[7] = fmaf(alB, v1.w, acc[7]);
        }
        float4 b0 = *(const float4*)(bias + cA);
        float4 b1 = *(const float4*)(bias + cB);
        float4 o0, o1;
        o0.x = acc[0] + b0.x; o0.y = acc[1] + b0.y; o0.z = acc[2] + b0.z; o0.w = acc[3] + b0.w;
        o1.x = acc[4] + b1.x; o1.y = acc[5] + b1.y; o1.z = acc[6] + b1.z; o1.w = acc[7] + b1.w;
        if (DO_ELU) {
            o0.x = elu(o0.x); o0.y = elu(o0.y); o0.z = elu(o0.z); o0.w = elu(o0.w);
            o1.x = elu(o1.x); o1.y = elu(o1.y); o1.z = elu(o1.z); o1.w = elu(o1.w);
        }
        float* op = out + (size_t)n * 256;
        *(float4*)(op + cA) = o0;
        *(float4*)(op + cB) = o1;
    } else {
        // H == 1, CT == 128
        float adn = ald[n];
        float m = -INFINITY;
        for (int i = beg + lane; i < end; i += 32) {
            int s = g_csr[i];
            m = fmaxf(m, lrelu(als[s] + adn));
        }
#pragma unroll
        for (int o = 16; o; o >>= 1) m = fmaxf(m, __shfl_xor_sync(0xffffffffu, m, o));
        float den = 0.f;
        for (int i = beg + lane; i < end; i += 32) {
            int s = g_csr[i];
            den += __expf(lrelu(als[s] + adn) - m);
        }
#pragma unroll
        for (int o = 16; o; o >>= 1) den += __shfl_xor_sync(0xffffffffu, den, o);
        float iv = 1.f / (den + 1e-16f);
        const int cA = lane * 4;
        float acc[4] = {0.f, 0.f, 0.f, 0.f};
        for (int i = beg; i < end; i++) {
            int s = g_csr[i];
            float al = __expf(lrelu(als[s] + adn) - m) * iv;
            float4 v = *(const float4*)(h + (size_t)s * 128 + cA);
            acc[0] = fmaf(al, v.x, acc[0]); acc[1] = fmaf(al, v.y, acc[1]);
            acc[2] = fmaf(al, v.z, acc[2]); acc[3] = fmaf(al, v.w, acc[3]);
        }
        float4 bv = *(const float4*)(bias + cA);
        float4 o0;
        o0.x = acc[0] + bv.x; o0.y = acc[1] + bv.y;
        o0.z = acc[2] + bv.z; o0.w = acc[3] + bv.w;
        *(float4*)(out + (size_t)n * 128 + cA) = o0;
    }
}

// ---------------- launch ----------------
extern "C" void kernel_launch(void* const* d_in, const int* in_sizes, int n_in,
                              void* d_out, int out_size) {
    const float* x   = (const float*)d_in[0];
    const void*  ei  = d_in[1];              // int32 or int64, probed on device
    const float* W0  = (const float*)d_in[2];
    const float* as0 = (const float*)d_in[3];
    const float* ad0 = (const float*)d_in[4];
    const float* b0  = (const float*)d_in[5];
    const float* W1  = (const float*)d_in[6];
    const float* as1 = (const float*)d_in[7];
    const float* ad1 = (const float*)d_in[8];
    const float* b1  = (const float*)d_in[9];
    const float* W2  = (const float*)d_in[10];
    const float* as2 = (const float*)d_in[11];
    const float* ad2 = (const float*)d_in[12];
    const float* b2  = (const float*)d_in[13];
    float* out = (float*)d_out;

    const int TB = 256;
    const int gN = (NN + TB - 1) / TB;
    const int gE = (EE + TB - 1) / TB;
    const int gW = (NN + 7) / 8;   // warp-per-node kernels, 8 warps/block

    // dtype probe + CSR build (shared by all 3 layers)
    k_detect<<<1, 32>>>((const int*)ei);
    k_init_deg<<<gN, TB>>>();
    k_count_edges<<<gE, TB>>>(ei);
    k_scan<<<1, 1024>>>();
    k_scatter_self<<<gN, TB>>>();
    k_scatter_edges<<<gE, TB>>>(ei);

    dim3 gemmGrid2((NN + 127) / 128, 2);
    dim3 gemmGrid1((NN + 127) / 128, 1);

    // layer 0: x[N,128] @ W0[128,256] -> g_h
    k_sgemm<true><<<gemmGrid2, 256>>>(x, W0, NN, F0, HID);
    k_scores<256, 4><<<gW, TB>>>(as0, ad0);
    k_agg<256, 4, true, false><<<gW, TB>>>(b0, nullptr);

    // layer 1: g_agg[N,256] @ W1[256,256] -> g_h
    k_sgemm<false><<<gemmGrid2, 256>>>(nullptr, W1, NN, HID, HID);
    k_scores<256, 4><<<gW, TB>>>(as1, ad1);
    k_agg<256, 4, true, false><<<gW, TB>>>(b1, nullptr);

    // layer 2: g_agg[N,256] @ W2[256,128] -> g_h, 1 head, no ELU, write d_out
    k_sgemm<false><<<gemmGrid1, 256>>>(nullptr, W2, NN, HID, OUTC);
    k_scores<128, 1><<<gW, TB>>>(as2, ad2);
    k_agg<128, 1, false, true><<<gW, TB>>>(b2, out);
}